// round 2
// baseline (speedup 1.0000x reference)
#include <cuda_runtime.h>

// Scratch: q/kv projections (fp32). Pixel linear order: ((b*64+P)*64+R)*16 + (i*4+j)
// where P = W-block, R = H-block, i = w-offset, j = h-offset.
__device__ __align__(16) float g_q [2u*64*64*16*256];  // 134 MB
__device__ __align__(16) float g_kv[2u*64*64*16*512];  // 268 MB

__device__ __forceinline__ float ex2f(float x) {
    float y; asm("ex2.approx.ftz.f32 %0, %1;" : "=f"(y) : "f"(x)); return y;
}

// ---------------------------------------------------------------------------
// Pass 1: proj = x @ w_in.T + b_in   (M=131072 px, N=768, K=128)
// CTA: 64 pixels (one b,P, four R blocks) x 768 outputs. 256 threads.
// ---------------------------------------------------------------------------
__global__ void proj_kernel(const float* __restrict__ x,
                            const float* __restrict__ w_in,
                            const float* __restrict__ b_in)
{
    __shared__ float  xs[64 * 128];   // [m][k], m = Rl*16 + i*4 + j
    __shared__ float4 ws4[64 * 16];   // [n][k4 ^ (n&15)] for one 64-wide K half

    const int t   = blockIdx.x;
    const int b   = t >> 10;
    const int P   = (t >> 4) & 63;
    const int R0  = (t & 15) << 2;
    const int tid = threadIdx.x;

    // Stage x tile: 128 ch x 16 (Rl,j) rows, float4 across i (w direction)
    const float* xb = x + b * 128 * 65536;
    #pragma unroll
    for (int ii = 0; ii < 8; ii++) {
        int idx = tid + ii * 256;            // 0..2047
        int c  = idx >> 4;
        int rj = idx & 15;
        int Rl = rj >> 2, j = rj & 3;
        int hh = (R0 + Rl) * 4 + j;
        float4 v = *(const float4*)(xb + (c * 256 + hh) * 256 + P * 4);
        int mb_ = Rl * 16 + j;
        xs[(mb_ + 0)  * 128 + c] = v.x;
        xs[(mb_ + 4)  * 128 + c] = v.y;
        xs[(mb_ + 8)  * 128 + c] = v.z;
        xs[(mb_ + 12) * 128 + c] = v.w;
    }

    const int tn = tid & 15;
    const int tm = tid >> 4;
    const int blk = ((b * 64 + P) * 64 + R0) * 16;   // pixel-lin base; pixel = blk + m
    const float4* xs4 = (const float4*)xs;

    for (int nc = 0; nc < 12; nc++) {
        const int n0 = nc * 64;
        float acc[4][4];
        #pragma unroll
        for (int mm = 0; mm < 4; mm++)
            #pragma unroll
            for (int nn = 0; nn < 4; nn++) acc[mm][nn] = 0.f;

        for (int kc = 0; kc < 2; kc++) {
            __syncthreads();
            // stage w chunk: rows n0..n0+63, K half kc (64 floats = 16 float4)
            #pragma unroll
            for (int ii = 0; ii < 4; ii++) {
                int idx = tid + ii * 256;    // 0..1023
                int n = idx >> 4, kq = idx & 15;
                float4 v = *(const float4*)(w_in + (n0 + n) * 128 + kc * 64 + kq * 4);
                ws4[n * 16 + (kq ^ (n & 15))] = v;
            }
            __syncthreads();

            #pragma unroll
            for (int k4 = 0; k4 < 16; k4++) {
                float4 a[4], bb[4];
                #pragma unroll
                for (int mm = 0; mm < 4; mm++)
                    a[mm] = xs4[(tm + 16 * mm) * 32 + kc * 16 + k4];
                #pragma unroll
                for (int nn = 0; nn < 4; nn++) {
                    int n = tn + 16 * nn;
                    bb[nn] = ws4[n * 16 + (k4 ^ (n & 15))];
                }
                #pragma unroll
                for (int mm = 0; mm < 4; mm++)
                    #pragma unroll
                    for (int nn = 0; nn < 4; nn++) {
                        acc[mm][nn] += a[mm].x * bb[nn].x;
                        acc[mm][nn] += a[mm].y * bb[nn].y;
                        acc[mm][nn] += a[mm].z * bb[nn].z;
                        acc[mm][nn] += a[mm].w * bb[nn].w;
                    }
            }
        }

        // writeback (+ bias); n stride 16 -> 64B contiguous per half-warp
        #pragma unroll
        for (int nn = 0; nn < 4; nn++) {
            int n = n0 + tn + 16 * nn;
            float bi = __ldg(b_in + n);
            #pragma unroll
            for (int mm = 0; mm < 4; mm++) {
                int m = tm + 16 * mm;
                float v = acc[mm][nn] + bi;
                if (n < 256) g_q [(blk + m) * 256 + n]         = v;
                else         g_kv[(blk + m) * 512 + (n - 256)] = v;
            }
        }
    }
}

// ---------------------------------------------------------------------------
// Pass 2: attention over 3x3 neighbor blocks + fused output projection.
// One CTA per (b,P,R) block. 128 threads: thread = (head h, query row qq).
// ---------------------------------------------------------------------------
__global__ __launch_bounds__(128) void attn_kernel(
    const float* __restrict__ w_out, const float* __restrict__ b_out,
    const float* __restrict__ pce,   float* __restrict__ out)
{
    __shared__ float pool[16 * 256 * 2 + 2048];   // kbuf | vbuf | pcesm (obuf reuses k/v)
    float* kbuf  = pool;
    float* vbuf  = pool + 4096;
    float* pcesm = pool + 8192;

    const int bx = blockIdx.x;
    const int b  = bx >> 12;
    const int P  = (bx >> 6) & 63;
    const int R  = bx & 63;
    const int tid = threadIdx.x;
    const int h  = tid >> 4;
    const int qq = tid & 15;
    const int iq = qq >> 2, jq = qq & 3;

    const float LOG2E = 1.4426950408889634f;
    for (int i = tid; i < 2048; i += 128) pcesm[i] = pce[i] * LOG2E;

    // q row in registers, pre-scaled by (1/sqrt(DH)) * log2(e)
    const float SC = 0.17677669529663687f * LOG2E;
    float q[32];
    {
        const float4* qp = (const float4*)(g_q + (((b * 64 + P) * 64 + R) * 16 + qq) * 256 + h * 32);
        #pragma unroll
        for (int d4 = 0; d4 < 8; d4++) {
            float4 v = qp[d4];
            q[d4*4+0] = v.x * SC; q[d4*4+1] = v.y * SC;
            q[d4*4+2] = v.z * SC; q[d4*4+3] = v.w * SC;
        }
    }

    float acc[32];
    #pragma unroll
    for (int d = 0; d < 32; d++) acc[d] = 0.f;
    float mrun = -1e30f;
    float l = 0.f;

    __syncthreads();   // pcesm ready

    for (int dp = 0; dp < 3; dp++) {
        int Pp = P + dp - 1;
        if (Pp < 0 || Pp > 63) continue;
        for (int dr = 0; dr < 3; dr++) {
            int Rp = R + dr - 1;
            if (Rp < 0 || Rp > 63) continue;   // exactly the boundary mask (-inf cut)

            __syncthreads();  // previous tile fully consumed
            const float4* src = (const float4*)(g_kv + (((b * 64 + Pp) * 64 + Rp) * 16) * 512);
            float4* kb4 = (float4*)kbuf;
            float4* vb4 = (float4*)vbuf;
            #pragma unroll
            for (int ii = 0; ii < 16; ii++) {
                int idx = tid + ii * 128;      // 0..2047
                int pix = idx >> 7;
                int c4  = idx & 127;
                float4 v = src[idx];
                if (c4 < 64) kb4[pix * 64 + c4]        = v;
                else         vb4[pix * 64 + (c4 - 64)] = v;
            }
            __syncthreads();

            float s[16];
            #pragma unroll
            for (int kp = 0; kp < 16; kp++) {
                const float4* kr = (const float4*)(kbuf + kp * 256 + h * 32);
                float d0 = 0.f, d1 = 0.f;
                #pragma unroll
                for (int d4 = 0; d4 < 8; d4++) {
                    float4 kk = kr[d4];
                    d0 += q[d4*4+0] * kk.x + q[d4*4+2] * kk.z;
                    d1 += q[d4*4+1] * kk.y + q[d4*4+3] * kk.w;
                }
                int ik = kp >> 2, jk = kp & 3;
                int nu = dp * 4 + ik + 4 - iq;
                int nt = dr * 4 + jk + 4 - jq;
                s[kp] = (d0 + d1) - pcesm[h * 256 + nu * 16 + nt];
            }

            float mb = s[0];
            #pragma unroll
            for (int kp = 1; kp < 16; kp++) mb = fmaxf(mb, s[kp]);
            float mn = fmaxf(mrun, mb);
            float f  = ex2f(mrun - mn);
            mrun = mn;
            l *= f;
            #pragma unroll
            for (int d = 0; d < 32; d++) acc[d] *= f;

            #pragma unroll
            for (int kp = 0; kp < 16; kp++) {
                float p = ex2f(s[kp] - mn);
                l += p;
                const float4* vr = (const float4*)(vbuf + kp * 256 + h * 32);
                #pragma unroll
                for (int d4 = 0; d4 < 8; d4++) {
                    float4 vv = vr[d4];
                    acc[d4*4+0] += p * vv.x;
                    acc[d4*4+1] += p * vv.y;
                    acc[d4*4+2] += p * vv.z;
                    acc[d4*4+3] += p * vv.w;
                }
            }
        }
    }

    // Normalize and stage attention output: obuf[qq][h*32+d], row stride 260
    __syncthreads();                    // all kv reads done; obuf aliases kbuf/vbuf
    float* obuf = pool;
    {
        float inv = 1.0f / l;
        float4* orow = (float4*)(obuf + qq * 260 + h * 32);
        #pragma unroll
        for (int d4 = 0; d4 < 8; d4++) {
            float4 v;
            v.x = acc[d4*4+0] * inv; v.y = acc[d4*4+1] * inv;
            v.z = acc[d4*4+2] * inv; v.w = acc[d4*4+3] * inv;
            orow[d4] = v;
        }
    }
    __syncthreads();

    // Fused output projection: out16x128 = obuf(16x256) @ w_out.T + b_out
    // thread = (j, cg): 4 channels x 4 w-positions; float4 stores along W.
    const int j  = tid & 3;
    const int cg = tid >> 2;            // 0..31
    float accO[4][4];
    #pragma unroll
    for (int ci = 0; ci < 4; ci++)
        #pragma unroll
        for (int i = 0; i < 4; i++) accO[ci][i] = 0.f;

    #pragma unroll 8
    for (int k4 = 0; k4 < 64; k4++) {
        float4 o[4];
        #pragma unroll
        for (int i = 0; i < 4; i++)
            o[i] = *(const float4*)(obuf + (i * 4 + j) * 260 + k4 * 4);
        #pragma unroll
        for (int ci = 0; ci < 4; ci++) {
            float4 w4 = __ldg((const float4*)(w_out + (cg * 4 + ci) * 256 + k4 * 4));
            #pragma unroll
            for (int i = 0; i < 4; i++)
                accO[ci][i] += w4.x * o[i].x + w4.y * o[i].y
                             + w4.z * o[i].z + w4.w * o[i].w;
        }
    }

    #pragma unroll
    for (int ci = 0; ci < 4; ci++) {
        int c = cg * 4 + ci;
        float bo = __ldg(b_out + c);
        float4 r;
        r.x = accO[ci][0] + bo; r.y = accO[ci][1] + bo;
        r.z = accO[ci][2] + bo; r.w = accO[ci][3] + bo;
        *(float4*)(out + ((b * 128 + c) * 256 + (R * 4 + j)) * 256 + P * 4) = r;
    }
}

// ---------------------------------------------------------------------------
extern "C" void kernel_launch(void* const* d_in, const int* in_sizes, int n_in,
                              void* d_out, int out_size)
{
    const float* x     = (const float*)d_in[0];
    const float* w_in  = (const float*)d_in[1];
    const float* b_in  = (const float*)d_in[2];
    const float* w_out = (const float*)d_in[3];
    const float* b_out = (const float*)d_in[4];
    const float* pce   = (const float*)d_in[5];
    float* out = (float*)d_out;

    proj_kernel<<<2048, 256>>>(x, w_in, b_in);
    attn_kernel<<<8192, 128>>>(w_out, b_out, pce, out);
}